// round 6
// baseline (speedup 1.0000x reference)
#include <cuda_runtime.h>
#include <cuda_fp16.h>
#include <cstdint>

// Problem dims
#define NB 8
#define NS 4096
#define NF 256
#define NI 512
#define NI3 1536
#define ND 4
#define NKT 7
#define NV 256

#define RSTRIDE 40   // half-elements per smem row (80B) -> conflict-free ldmatrix
#define BM 128
#define BN 256
#define STAGES 3
#define A_STAGE_B (BM * RSTRIDE * 2)          // 10240 B
#define B_STAGE_B (BN * RSTRIDE * 2)          // 20480 B
#define SMEM_DYN (STAGES * (A_STAGE_B + B_STAGE_B))  // 92160 B

// ---------------- device scratch ----------------
__device__ float g_P[(size_t)NB * NF * NS];            // [b][c][s]
__device__ float g_Q[(size_t)NB * NF * NS];            // [b][c][s]
__device__ float g_y[(size_t)NB * NI3 * NS];           // [b][c][s]
__device__ float g_v[(size_t)NB * NI * NS];            // [b][i][s]
__device__ __half g_xth[(size_t)NB * NS * NF];         // [b][s][256] fp16
__device__ __half g_vth[(size_t)NB * NS * NI];         // [b][s][512] fp16 (also concat dst)
__device__ __half g_w1h[(size_t)ND * NKT * NI3 * NI];  // [d][tap][o][i] fp16
__device__ __half g_w0h[(size_t)ND * NI3 * NF];
__device__ __half g_w2h[(size_t)ND * NF * NI];
__device__ __half g_owh[(size_t)NV * 2 * NF];

// ---------------- helpers ----------------
__device__ __forceinline__ uint32_t cvta_s(const void* p) {
    return (uint32_t)__cvta_generic_to_shared(p);
}
__device__ __forceinline__ void cpa16(uint32_t dst, const void* src, int sz) {
    asm volatile("cp.async.cg.shared.global [%0], [%1], 16, %2;"
                 :: "r"(dst), "l"(src), "r"(sz));
}
__device__ __forceinline__ void cp_commit() { asm volatile("cp.async.commit_group;"); }
__device__ __forceinline__ void cp_wait1() { asm volatile("cp.async.wait_group 1;"); }
__device__ __forceinline__ void cp_wait0() { asm volatile("cp.async.wait_group 0;"); }

__device__ __forceinline__ void ldm_x4(uint32_t r[4], uint32_t addr) {
    asm volatile("ldmatrix.sync.aligned.m8n8.x4.shared.b16 {%0,%1,%2,%3}, [%4];"
                 : "=r"(r[0]), "=r"(r[1]), "=r"(r[2]), "=r"(r[3]) : "r"(addr));
}
__device__ __forceinline__ void mma_f16(float c[4], const uint32_t a[4],
                                        uint32_t b0, uint32_t b1) {
    asm volatile(
        "mma.sync.aligned.m16n8k16.row.col.f32.f16.f16.f32 "
        "{%0,%1,%2,%3}, {%4,%5,%6,%7}, {%8,%9}, {%0,%1,%2,%3};"
        : "+f"(c[0]), "+f"(c[1]), "+f"(c[2]), "+f"(c[3])
        : "r"(a[0]), "r"(a[1]), "r"(a[2]), "r"(a[3]), "r"(b0), "r"(b1));
}
__device__ __forceinline__ float mishf(float x) {
    if (x > 20.0f) return x;
    float t = __expf(x);
    float u = t * t + 2.0f * t;
    return x * (u / (u + 2.0f));
}

// ---------------- embedding gather ----------------
__global__ void embed_kernel(const int* __restrict__ inp, const float* __restrict__ emb) {
    int sx = threadIdx.x & 63, cg = threadIdx.x >> 6;
    int s = blockIdx.x * 64 + sx;
    int b = blockIdx.y;
    int idx = inp[b * NS + s];
    const float* er = emb + (size_t)idx * (2 * NF);
#pragma unroll 4
    for (int c = cg; c < NF; c += 4) {
        g_P[((size_t)b * NF + c) * NS + s] = er[c];
        g_Q[((size_t)b * NF + c) * NS + s] = er[c + NF];
    }
}

// ---------------- weight converts ----------------
__global__ void cvt_half_kernel(const float* __restrict__ src, __half* __restrict__ dst,
                                size_t n) {
    size_t i = (size_t)blockIdx.x * 256 + threadIdx.x;
    if (i < n) dst[i] = __float2half(src[i]);
}
// w1 [d][o][i][k] -> [d][k][o][i] fp16
__global__ void w1h_kernel(const float* __restrict__ w1) {
    size_t idx = (size_t)blockIdx.x * 256 + threadIdx.x;
    int i = (int)(idx & (NI - 1));
    size_t r = idx / NI;
    int o = (int)(r % NI3);
    r /= NI3;
    int t = (int)(r % NKT);
    int d = (int)(r / NKT);
    g_w1h[idx] = __float2half(w1[(((size_t)d * NI3 + o) * NI + i) * NKT + t]);
}

// ---------------- activation transpose+convert [b][C][S] f32 -> dst half [b][s][dstride]+doff ----------------
__global__ void transpose_h_kernel(const float* __restrict__ src, __half* __restrict__ dst,
                                   int C, int dstride, int doff) {
    __shared__ float tl[32][33];
    int b = blockIdx.z, c0 = blockIdx.y * 32, s0 = blockIdx.x * 32;
    int tx = threadIdx.x, ty = threadIdx.y;
#pragma unroll
    for (int q = 0; q < 4; q++) {
        int c = ty + q * 8;
        tl[c][tx] = src[((size_t)b * C + c0 + c) * NS + s0 + tx];
    }
    __syncthreads();
#pragma unroll
    for (int q = 0; q < 4; q++) {
        int s = ty + q * 8;
        dst[((size_t)b * NS + s0 + s) * dstride + doff + c0 + tx] = __float2half(tl[tx][s]);
    }
}

// ---------------- lin_attn ----------------
__global__ void linattn_kernel() {
    int i = blockIdx.x, b = blockIdx.y, t = threadIdx.x;
    const float* dr = g_y + ((size_t)b * NI3 + i) * NS + t * 16;
    const float* sc = g_y + ((size_t)b * NI3 + NI + i) * NS + t * 16;
    const float* sh = g_y + ((size_t)b * NI3 + 2 * NI + i) * NS + t * 16;
    float* op = g_v + ((size_t)b * NI + i) * NS + t * 16;

    float loc[16];
#pragma unroll
    for (int q = 0; q < 4; q++) {
        float4 f = ((const float4*)dr)[q];
        loc[q * 4 + 0] = f.x; loc[q * 4 + 1] = f.y;
        loc[q * 4 + 2] = f.z; loc[q * 4 + 3] = f.w;
    }
#pragma unroll
    for (int j = 1; j < 16; j++) loc[j] += loc[j - 1];
    float tot = loc[15];

    float v = tot;
#pragma unroll
    for (int o = 1; o < 32; o <<= 1) {
        float n = __shfl_up_sync(0xffffffffu, v, o);
        if ((t & 31) >= o) v += n;
    }
    __shared__ float wsum[8];
    if ((t & 31) == 31) wsum[t >> 5] = v;
    __syncthreads();
    if (t == 0) {
        float run = 0.0f;
#pragma unroll
        for (int k = 0; k < 8; k++) { float w = wsum[k]; wsum[k] = run; run += w; }
    }
    __syncthreads();
    float excl = wsum[t >> 5] + (v - tot);

    int sbase = t * 16;
#pragma unroll
    for (int q = 0; q < 4; q++) {
        float4 scv = ((const float4*)sc)[q];
        float4 shv = ((const float4*)sh)[q];
        float4 o4;
        o4.x = (excl + loc[q * 4 + 0]) / (float)(sbase + q * 4 + 1) * scv.x + shv.x;
        o4.y = (excl + loc[q * 4 + 1]) / (float)(sbase + q * 4 + 2) * scv.y + shv.y;
        o4.z = (excl + loc[q * 4 + 2]) / (float)(sbase + q * 4 + 3) * scv.z + shv.z;
        o4.w = (excl + loc[q * 4 + 3]) / (float)(sbase + q * 4 + 4) * scv.w + shv.w;
        ((float4*)op)[q] = o4;
    }
}

// ---------------- fp16 warp-MMA GEMM: 128x256 block, 64x64 warp tile, 3-stage cp.async ----------------
// C[M x Nseq] = A[M x K] * B[K x Nseq] per batch. k-step = 32.
// conv: A = g_w1h slice [tap][o][i], B rows tap-shifted with causal zero-fill.
// cmode: 0 -> g_y = mish(acc); 1 -> g_P += acc; 2 -> g_Q += acc; 3 -> Cext = acc + bias.
__global__ void __launch_bounds__(256, 1) hgemm(
    const __half* __restrict__ A, int lda, int conv,
    const __half* __restrict__ B, int bstride, int KT,
    int cmode, float* __restrict__ Cext, const float* __restrict__ bias)
{
    extern __shared__ __align__(16) char dsm[];
    uint32_t sbase = cvta_s(dsm);

    int t = threadIdx.x, lane = t & 31, warp = t >> 5;
    int n0 = blockIdx.x * BN, m0 = blockIdx.y * BM, b = blockIdx.z;
    int wm = (warp >> 2) * 64, wn = (warp & 3) * 64;

    float acc[4][8][4];
#pragma unroll
    for (int mi = 0; mi < 4; mi++)
#pragma unroll
        for (int ni = 0; ni < 8; ni++)
#pragma unroll
            for (int q = 0; q < 4; q++) acc[mi][ni][q] = 0.0f;

    // A fill: thread -> row t>>1, 16B-chunks {0,1} or {2,3}
    int a_lrow = t >> 1, a_lch = (t & 1) * 2;
    // B fill: thread -> row t, all 4 chunks

    auto issue = [&](int kt) {
        int st = kt % STAGES;
        uint32_t ad = sbase + st * A_STAGE_B + a_lrow * (RSTRIDE * 2) + a_lch * 16;
        uint32_t bd = sbase + STAGES * A_STAGE_B + st * B_STAGE_B + t * (RSTRIDE * 2);
        const __half *asrc, *bsrc;
        int bsz = 16;
        if (conv) {
            int tap = kt >> 4, ic = (kt & 15) * 32;
            asrc = A + ((size_t)tap * NI3 + m0 + a_lrow) * NI + ic + a_lch * 8;
            int s = n0 + t + tap - (NKT - 1);
            bsrc = B + ((size_t)b * NS + (s < 0 ? 0 : s)) * bstride + ic;
            bsz = (s < 0) ? 0 : 16;
        } else {
            asrc = A + (size_t)(m0 + a_lrow) * lda + kt * 32 + a_lch * 8;
            bsrc = B + ((size_t)b * NS + n0 + t) * bstride + kt * 32;
        }
        cpa16(ad, asrc, 16);
        cpa16(ad + 16, asrc + 8, 16);
#pragma unroll
        for (int u = 0; u < 4; u++) cpa16(bd + u * 16, bsrc + u * 8, bsz);
        cp_commit();
    };

    // ldmatrix lane addressing
    int a_row = (lane & 7) + 8 * ((lane >> 3) & 1);   // 0..15
    int a_kb = lane >> 4;                             // 0..1 (16B k-halves)
    int b_coff = (lane & 7) + 8 * (lane >> 4);        // n offset 0..15
    int b_kb = (lane >> 3) & 1;                       // 0..1

    issue(0);
    if (KT > 1) issue(1);
    for (int kt = 0; kt < KT; kt++) {
        if (kt + 1 < KT) cp_wait1(); else cp_wait0();
        __syncthreads();
        if (kt + 2 < KT) issue(kt + 2);
        int st = kt % STAGES;
        uint32_t aT = sbase + st * A_STAGE_B;
        uint32_t bT = sbase + STAGES * A_STAGE_B + st * B_STAGE_B;
#pragma unroll
        for (int sub = 0; sub < 2; sub++) {
            uint32_t af[4][4];
#pragma unroll
            for (int mi = 0; mi < 4; mi++) {
                uint32_t addr = aT +
                    (wm + mi * 16 + a_row) * (RSTRIDE * 2) + sub * 32 + a_kb * 16;
                ldm_x4(af[mi], addr);
            }
            uint32_t bf[4][4];
#pragma unroll
            for (int g = 0; g < 4; g++) {
                uint32_t addr = bT +
                    (wn + g * 16 + b_coff) * (RSTRIDE * 2) + sub * 32 + b_kb * 16;
                ldm_x4(bf[g], addr);
            }
#pragma unroll
            for (int mi = 0; mi < 4; mi++)
#pragma unroll
                for (int ni = 0; ni < 8; ni++)
                    mma_f16(acc[mi][ni], af[mi], bf[ni >> 1][(ni & 1) * 2],
                            bf[ni >> 1][(ni & 1) * 2 + 1]);
        }
        __syncthreads();
    }

    // epilogue: rows mlo, mlo+8; cols n, n+1
#pragma unroll
    for (int mi = 0; mi < 4; mi++) {
        int mlo = m0 + wm + mi * 16 + (lane >> 2);
#pragma unroll
        for (int ni = 0; ni < 8; ni++) {
            int n = n0 + wn + ni * 8 + 2 * (lane & 3);
            float* cc = acc[mi][ni];
#pragma unroll
            for (int hh = 0; hh < 2; hh++) {
                int m = mlo + hh * 8;
                float v0 = cc[hh * 2 + 0], v1 = cc[hh * 2 + 1];
                if (cmode == 0) {
                    float2 o = make_float2(mishf(v0), mishf(v1));
                    *(float2*)(g_y + ((size_t)b * NI3 + m) * NS + n) = o;
                } else if (cmode == 1 || cmode == 2) {
                    float* X = (cmode == 1) ? g_P : g_Q;
                    float2* p = (float2*)(X + ((size_t)b * NF + m) * NS + n);
                    float2 e = *p;
                    e.x += v0; e.y += v1;
                    *p = e;
                } else {
                    float bb = bias[m];
                    float2 o = make_float2(v0 + bb, v1 + bb);
                    *(float2*)(Cext + ((size_t)b * NV + m) * NS + n) = o;
                }
            }
        }
    }
}

// ---------------- launch ----------------
extern "C" void kernel_launch(void* const* d_in, const int* in_sizes, int n_in,
                              void* d_out, int out_size) {
    (void)in_sizes; (void)n_in; (void)out_size;
    const int* inp = (const int*)d_in[0];
    const float* emb = (const float*)d_in[1];
    const float* w0 = (const float*)d_in[2];
    const float* w1 = (const float*)d_in[3];
    const float* w2 = (const float*)d_in[4];
    const float* out_w = (const float*)d_in[5];
    const float* out_b = (const float*)d_in[6];
    float* out = (float*)d_out;

    float* gP; cudaGetSymbolAddress((void**)&gP, g_P);
    float* gQ; cudaGetSymbolAddress((void**)&gQ, g_Q);
    float* gV; cudaGetSymbolAddress((void**)&gV, g_v);
    __half* gXTH; cudaGetSymbolAddress((void**)&gXTH, g_xth);
    __half* gVTH; cudaGetSymbolAddress((void**)&gVTH, g_vth);
    __half* gW1H; cudaGetSymbolAddress((void**)&gW1H, g_w1h);
    __half* gW0H; cudaGetSymbolAddress((void**)&gW0H, g_w0h);
    __half* gW2H; cudaGetSymbolAddress((void**)&gW2H, g_w2h);
    __half* gOWH; cudaGetSymbolAddress((void**)&gOWH, g_owh);

    cudaFuncSetAttribute(hgemm, cudaFuncAttributeMaxDynamicSharedMemorySize, SMEM_DYN);

    embed_kernel<<<dim3(NS / 64, NB), 256>>>(inp, emb);
    w1h_kernel<<<(int)(((size_t)ND * NKT * NI3 * NI) / 256), 256>>>(w1);
    {
        size_t n0c = (size_t)ND * NI3 * NF;
        cvt_half_kernel<<<(int)((n0c + 255) / 256), 256>>>(w0, gW0H, n0c);
        size_t n2c = (size_t)ND * NF * NI;
        cvt_half_kernel<<<(int)((n2c + 255) / 256), 256>>>(w2, gW2H, n2c);
        size_t noc = (size_t)NV * 2 * NF;
        cvt_half_kernel<<<(int)((noc + 255) / 256), 256>>>(out_w, gOWH, noc);
    }

    dim3 tb(32, 8);
    for (int d = 0; d < ND; d++) {
        const float* xin = (d % 2 == 0) ? gQ : gP;
        int accm = (d % 2 == 0) ? 1 : 2;

        transpose_h_kernel<<<dim3(NS / 32, NF / 32, NB), tb>>>(xin, gXTH, NF, NF, 0);
        hgemm<<<dim3(NS / BN, NI3 / BM, NB), 256, SMEM_DYN>>>(
            gW0H + (size_t)d * NI3 * NF, NF, 0, gXTH, NF, NF / 32, 0, nullptr, nullptr);
        linattn_kernel<<<dim3(NI, NB), 256>>>();

        transpose_h_kernel<<<dim3(NS / 32, NI / 32, NB), tb>>>(gV, gVTH, NI, NI, 0);
        hgemm<<<dim3(NS / BN, NI3 / BM, NB), 256, SMEM_DYN>>>(
            gW1H + (size_t)d * NKT * NI3 * NI, NI, 1, gVTH, NI, NKT * NI / 32,
            0, nullptr, nullptr);
        linattn_kernel<<<dim3(NI, NB), 256>>>();

        transpose_h_kernel<<<dim3(NS / 32, NI / 32, NB), tb>>>(gV, gVTH, NI, NI, 0);
        hgemm<<<dim3(NS / BN, NF / BM, NB), 256, SMEM_DYN>>>(
            gW2H + (size_t)d * NF * NI, NI, 0, gVTH, NI, NI / 32, accm, nullptr, nullptr);
    }

    // final: concat(P;Q) -> [b][s][512] half, then out = out_w @ concat + bias
    transpose_h_kernel<<<dim3(NS / 32, NF / 32, NB), tb>>>(gP, gVTH, NF, 2 * NF, 0);
    transpose_h_kernel<<<dim3(NS / 32, NF / 32, NB), tb>>>(gQ, gVTH, NF, 2 * NF, NF);
    hgemm<<<dim3(NS / BN, NV / BM, NB), 256, SMEM_DYN>>>(
        gOWH, 2 * NF, 0, gVTH, 2 * NF, 2 * NF / 32, 3, out, out_b);
}

// round 7
// speedup vs baseline: 1.3576x; 1.3576x over previous
#include <cuda_runtime.h>
#include <cuda_fp16.h>
#include <cstdint>

// Problem dims
#define NB 8
#define NS 4096
#define NF 256
#define NI 512
#define NI3 1536
#define ND 4
#define NKT 7
#define NV 256

#define RSTRIDE 40   // half-elements per smem row (80B) -> conflict-free ldmatrix
#define BM 128
#define BN 128
#define STAGES 3
#define A_STAGE_B (BM * RSTRIDE * 2)                 // 10240 B
#define B_STAGE_B (BN * RSTRIDE * 2)                 // 10240 B
#define SMEM_DYN (STAGES * (A_STAGE_B + B_STAGE_B))  // 61440 B

// ---------------- device scratch ----------------
__device__ float g_P[(size_t)NB * NF * NS];            // [b][c][s]
__device__ float g_Q[(size_t)NB * NF * NS];            // [b][c][s]
__device__ float g_y[(size_t)NB * NI3 * NS];           // [b][c][s]
__device__ float g_v[(size_t)NB * NI * NS];            // [b][i][s]
__device__ __half g_xth[(size_t)NB * NS * NF];         // [b][s][256] fp16
__device__ __half g_vth[(size_t)NB * NS * NI];         // [b][s][512] fp16 (also concat dst)
__device__ __half g_w1h[(size_t)ND * NKT * NI3 * NI];  // [d][tap][o][i] fp16
__device__ __half g_w0h[(size_t)ND * NI3 * NF];
__device__ __half g_w2h[(size_t)ND * NF * NI];
__device__ __half g_owh[(size_t)NV * 2 * NF];

// ---------------- helpers ----------------
__device__ __forceinline__ uint32_t cvta_s(const void* p) {
    return (uint32_t)__cvta_generic_to_shared(p);
}
__device__ __forceinline__ void cpa16(uint32_t dst, const void* src, int sz) {
    asm volatile("cp.async.cg.shared.global [%0], [%1], 16, %2;"
                 :: "r"(dst), "l"(src), "r"(sz));
}
__device__ __forceinline__ void cp_commit() { asm volatile("cp.async.commit_group;"); }
__device__ __forceinline__ void cp_wait1() { asm volatile("cp.async.wait_group 1;"); }
__device__ __forceinline__ void cp_wait0() { asm volatile("cp.async.wait_group 0;"); }

__device__ __forceinline__ void ldm_x4(uint32_t r[4], uint32_t addr) {
    asm volatile("ldmatrix.sync.aligned.m8n8.x4.shared.b16 {%0,%1,%2,%3}, [%4];"
                 : "=r"(r[0]), "=r"(r[1]), "=r"(r[2]), "=r"(r[3]) : "r"(addr));
}
__device__ __forceinline__ void mma_f16(float c[4], const uint32_t a[4],
                                        uint32_t b0, uint32_t b1) {
    asm volatile(
        "mma.sync.aligned.m16n8k16.row.col.f32.f16.f16.f32 "
        "{%0,%1,%2,%3}, {%4,%5,%6,%7}, {%8,%9}, {%0,%1,%2,%3};"
        : "+f"(c[0]), "+f"(c[1]), "+f"(c[2]), "+f"(c[3])
        : "r"(a[0]), "r"(a[1]), "r"(a[2]), "r"(a[3]), "r"(b0), "r"(b1));
}
__device__ __forceinline__ float mishf(float x) {
    if (x > 20.0f) return x;
    float t = __expf(x);
    float u = t * t + 2.0f * t;
    return x * (u / (u + 2.0f));
}

// ---------------- merged prep: w1 transpose+cvt, w0/w2/out_w cvt, embedding ----------------
#define NBLK_W1 ((int)(((size_t)ND * NKT * NI3 * NI) / 256))   // 86016
#define NBLK_W0 ((int)(((size_t)ND * NI3 * NF) / 256))          // 6144
#define NBLK_W2 ((int)(((size_t)ND * NF * NI) / 256))           // 2048
#define NBLK_OW ((int)(((size_t)NV * 2 * NF) / 256))            // 512
#define NBLK_EMB ((NS / 64) * NB)                               // 512
#define NBLK_PREP (NBLK_W1 + NBLK_W0 + NBLK_W2 + NBLK_OW + NBLK_EMB)

__global__ void prep_kernel(const int* __restrict__ inp, const float* __restrict__ emb,
                            const float* __restrict__ w0, const float* __restrict__ w1,
                            const float* __restrict__ w2, const float* __restrict__ ow) {
    int blk = blockIdx.x;
    int tid = threadIdx.x;
    if (blk < NBLK_W1) {
        size_t idx = (size_t)blk * 256 + tid;
        int i = (int)(idx & (NI - 1));
        size_t r = idx / NI;
        int o = (int)(r % NI3);
        r /= NI3;
        int t = (int)(r % NKT);
        int d = (int)(r / NKT);
        g_w1h[idx] = __float2half(w1[(((size_t)d * NI3 + o) * NI + i) * NKT + t]);
        return;
    }
    blk -= NBLK_W1;
    if (blk < NBLK_W0) {
        size_t i = (size_t)blk * 256 + tid;
        g_w0h[i] = __float2half(w0[i]);
        return;
    }
    blk -= NBLK_W0;
    if (blk < NBLK_W2) {
        size_t i = (size_t)blk * 256 + tid;
        g_w2h[i] = __float2half(w2[i]);
        return;
    }
    blk -= NBLK_W2;
    if (blk < NBLK_OW) {
        size_t i = (size_t)blk * 256 + tid;
        g_owh[i] = __float2half(ow[i]);
        return;
    }
    blk -= NBLK_OW;
    {
        int bx = blk & 63, b = blk >> 6;
        int sx = tid & 63, cg = tid >> 6;
        int s = bx * 64 + sx;
        int idx = inp[b * NS + s];
        const float* er = emb + (size_t)idx * (2 * NF);
#pragma unroll 4
        for (int c = cg; c < NF; c += 4) {
            g_P[((size_t)b * NF + c) * NS + s] = er[c];
            g_Q[((size_t)b * NF + c) * NS + s] = er[c + NF];
        }
    }
}

// ---------------- activation transpose+convert [b][C][S] f32 -> dst half [b][s][dstride]+doff ----------------
__global__ void transpose_h_kernel(const float* __restrict__ src, __half* __restrict__ dst,
                                   int C, int dstride, int doff) {
    __shared__ float tl[32][33];
    int b = blockIdx.z, c0 = blockIdx.y * 32, s0 = blockIdx.x * 32;
    int tx = threadIdx.x, ty = threadIdx.y;
#pragma unroll
    for (int q = 0; q < 4; q++) {
        int c = ty + q * 8;
        tl[c][tx] = src[((size_t)b * C + c0 + c) * NS + s0 + tx];
    }
    __syncthreads();
#pragma unroll
    for (int q = 0; q < 4; q++) {
        int s = ty + q * 8;
        dst[((size_t)b * NS + s0 + s) * dstride + doff + c0 + tx] = __float2half(tl[tx][s]);
    }
}

// ---------------- lin_attn ----------------
__global__ void linattn_kernel() {
    int i = blockIdx.x, b = blockIdx.y, t = threadIdx.x;
    const float* dr = g_y + ((size_t)b * NI3 + i) * NS + t * 16;
    const float* sc = g_y + ((size_t)b * NI3 + NI + i) * NS + t * 16;
    const float* sh = g_y + ((size_t)b * NI3 + 2 * NI + i) * NS + t * 16;
    float* op = g_v + ((size_t)b * NI + i) * NS + t * 16;

    float loc[16];
#pragma unroll
    for (int q = 0; q < 4; q++) {
        float4 f = ((const float4*)dr)[q];
        loc[q * 4 + 0] = f.x; loc[q * 4 + 1] = f.y;
        loc[q * 4 + 2] = f.z; loc[q * 4 + 3] = f.w;
    }
#pragma unroll
    for (int j = 1; j < 16; j++) loc[j] += loc[j - 1];
    float tot = loc[15];

    float v = tot;
#pragma unroll
    for (int o = 1; o < 32; o <<= 1) {
        float n = __shfl_up_sync(0xffffffffu, v, o);
        if ((t & 31) >= o) v += n;
    }
    __shared__ float wsum[8];
    if ((t & 31) == 31) wsum[t >> 5] = v;
    __syncthreads();
    if (t == 0) {
        float run = 0.0f;
#pragma unroll
        for (int k = 0; k < 8; k++) { float w = wsum[k]; wsum[k] = run; run += w; }
    }
    __syncthreads();
    float excl = wsum[t >> 5] + (v - tot);

    int sbase = t * 16;
#pragma unroll
    for (int q = 0; q < 4; q++) {
        float4 scv = ((const float4*)sc)[q];
        float4 shv = ((const float4*)sh)[q];
        float4 o4;
        o4.x = (excl + loc[q * 4 + 0]) / (float)(sbase + q * 4 + 1) * scv.x + shv.x;
        o4.y = (excl + loc[q * 4 + 1]) / (float)(sbase + q * 4 + 2) * scv.y + shv.y;
        o4.z = (excl + loc[q * 4 + 2]) / (float)(sbase + q * 4 + 3) * scv.z + shv.z;
        o4.w = (excl + loc[q * 4 + 3]) / (float)(sbase + q * 4 + 4) * scv.w + shv.w;
        ((float4*)op)[q] = o4;
    }
}

// ---------------- fp16 warp-MMA GEMM: 128x128 block, 64x32 warp tile, 3-stage cp.async ----------------
// C[M x Nseq] = A[M x K] * B[K x Nseq] per batch. k-step = 32.
// conv: A = g_w1h slice [tap][o][i], B rows tap-shifted with causal zero-fill.
// cmode: 0 -> g_y = mish(acc); 1 -> g_P += acc; 2 -> g_Q += acc; 3 -> Cext = acc + bias.
__global__ void __launch_bounds__(256, 2) hgemm(
    const __half* __restrict__ A, int lda, int conv,
    const __half* __restrict__ B, int bstride, int KT,
    int cmode, float* __restrict__ Cext, const float* __restrict__ bias)
{
    extern __shared__ __align__(16) char dsm[];
    uint32_t sbase = cvta_s(dsm);

    int t = threadIdx.x, lane = t & 31, warp = t >> 5;
    int n0 = blockIdx.x * BN, m0 = blockIdx.y * BM, b = blockIdx.z;
    int wm = (warp >> 2) * 64, wn = (warp & 3) * 32;

    float acc[4][4][4];
#pragma unroll
    for (int mi = 0; mi < 4; mi++)
#pragma unroll
        for (int ni = 0; ni < 4; ni++)
#pragma unroll
            for (int q = 0; q < 4; q++) acc[mi][ni][q] = 0.0f;

    int lrow = t >> 1;               // 0..127
    int lch = (t & 1) * 2;           // 16B chunks {0,1} or {2,3}

    auto issue = [&](int kt) {
        int st = kt % STAGES;
        uint32_t ad = sbase + st * (A_STAGE_B + B_STAGE_B) + lrow * (RSTRIDE * 2) + lch * 16;
        uint32_t bd = ad + A_STAGE_B;
        const __half *asrc, *bsrc;
        int bsz = 16;
        if (conv) {
            int tap = kt >> 4, ic = (kt & 15) * 32;
            asrc = A + ((size_t)tap * NI3 + m0 + lrow) * NI + ic + lch * 8;
            int s = n0 + lrow + tap - (NKT - 1);
            bsrc = B + ((size_t)b * NS + (s < 0 ? 0 : s)) * bstride + ic + lch * 8;
            bsz = (s < 0) ? 0 : 16;
        } else {
            asrc = A + (size_t)(m0 + lrow) * lda + kt * 32 + lch * 8;
            bsrc = B + ((size_t)b * NS + n0 + lrow) * bstride + kt * 32 + lch * 8;
        }
        cpa16(ad, asrc, 16);
        cpa16(ad + 16, asrc + 8, 16);
        cpa16(bd, bsrc, bsz);
        cpa16(bd + 16, bsrc + 8, bsz);
        cp_commit();
    };

    // ldmatrix lane addressing (A rows = m, B rows = n, both k-contiguous)
    int a_row = (lane & 7) + 8 * ((lane >> 3) & 1);   // 0..15
    int a_kb = lane >> 4;                             // 0..1 (16B k-halves)
    int b_coff = (lane & 7) + 8 * (lane >> 4);        // n offset 0..15
    int b_kb = (lane >> 3) & 1;                       // 0..1

    issue(0);
    if (KT > 1) issue(1);
    for (int kt = 0; kt < KT; kt++) {
        if (kt + 1 < KT) cp_wait1(); else cp_wait0();
        __syncthreads();
        if (kt + 2 < KT) issue(kt + 2);
        int st = kt % STAGES;
        uint32_t aT = sbase + st * (A_STAGE_B + B_STAGE_B);
        uint32_t bT = aT + A_STAGE_B;
#pragma unroll
        for (int sub = 0; sub < 2; sub++) {
            uint32_t af[4][4];
#pragma unroll
            for (int mi = 0; mi < 4; mi++) {
                uint32_t addr = aT +
                    (wm + mi * 16 + a_row) * (RSTRIDE * 2) + sub * 32 + a_kb * 16;
                ldm_x4(af[mi], addr);
            }
            uint32_t bf[2][4];
#pragma unroll
            for (int g = 0; g < 2; g++) {
                uint32_t addr = bT +
                    (wn + g * 16 + b_coff) * (RSTRIDE * 2) + sub * 32 + b_kb * 16;
                ldm_x4(bf[g], addr);
            }
#pragma unroll
            for (int mi = 0; mi < 4; mi++)
#pragma unroll
                for (int ni = 0; ni < 4; ni++)
                    mma_f16(acc[mi][ni], af[mi], bf[ni >> 1][(ni & 1) * 2],
                            bf[ni >> 1][(ni & 1) * 2 + 1]);
        }
        // no trailing sync: stage (kt+2)%3 fills can't collide with stage kt reads,
        // and the next top-of-loop sync orders everything else.
    }

    // epilogue: rows mlo, mlo+8; cols n, n+1
#pragma unroll
    for (int mi = 0; mi < 4; mi++) {
        int mlo = m0 + wm + mi * 16 + (lane >> 2);
#pragma unroll
        for (int ni = 0; ni < 4; ni++) {
            int n = n0 + wn + ni * 8 + 2 * (lane & 3);
            float* cc = acc[mi][ni];
#pragma unroll
            for (int hh = 0; hh < 2; hh++) {
                int m = mlo + hh * 8;
                float v0 = cc[hh * 2 + 0], v1 = cc[hh * 2 + 1];
                if (cmode == 0) {
                    float2 o = make_float2(mishf(v0), mishf(v1));
                    *(float2*)(g_y + ((size_t)b * NI3 + m) * NS + n) = o;
                } else if (cmode == 1 || cmode == 2) {
                    float* X = (cmode == 1) ? g_P : g_Q;
                    float2* p = (float2*)(X + ((size_t)b * NF + m) * NS + n);
                    float2 e = *p;
                    e.x += v0; e.y += v1;
                    *p = e;
                } else {
                    float bb = bias[m];
                    float2 o = make_float2(v0 + bb, v1 + bb);
                    *(float2*)(Cext + ((size_t)b * NV + m) * NS + n) = o;
                }
            }
        }
    }
}

// ---------------- launch ----------------
extern "C" void kernel_launch(void* const* d_in, const int* in_sizes, int n_in,
                              void* d_out, int out_size) {
    (void)in_sizes; (void)n_in; (void)out_size;
    const int* inp = (const int*)d_in[0];
    const float* emb = (const float*)d_in[1];
    const float* w0 = (const float*)d_in[2];
    const float* w1 = (const float*)d_in[3];
    const float* w2 = (const float*)d_in[4];
    const float* out_w = (const float*)d_in[5];
    const float* out_b = (const float*)d_in[6];
    float* out = (float*)d_out;

    float* gP; cudaGetSymbolAddress((void**)&gP, g_P);
    float* gQ; cudaGetSymbolAddress((void**)&gQ, g_Q);
    float* gV; cudaGetSymbolAddress((void**)&gV, g_v);
    __half* gXTH; cudaGetSymbolAddress((void**)&gXTH, g_xth);
    __half* gVTH; cudaGetSymbolAddress((void**)&gVTH, g_vth);
    __half* gW1H; cudaGetSymbolAddress((void**)&gW1H, g_w1h);
    __half* gW0H; cudaGetSymbolAddress((void**)&gW0H, g_w0h);
    __half* gW2H; cudaGetSymbolAddress((void**)&gW2H, g_w2h);
    __half* gOWH; cudaGetSymbolAddress((void**)&gOWH, g_owh);

    cudaFuncSetAttribute(hgemm, cudaFuncAttributeMaxDynamicSharedMemorySize, SMEM_DYN);

    // launch #1: all prep (embed + weight converts) in one kernel
    prep_kernel<<<NBLK_PREP, 256>>>(inp, emb, w0, w1, w2, out_w);

    dim3 tb(32, 8);
    for (int d = 0; d < ND; d++) {
        const float* xin = (d % 2 == 0) ? gQ : gP;
        int accm = (d % 2 == 0) ? 1 : 2;

        transpose_h_kernel<<<dim3(NS / 32, NF / 32, NB), tb>>>(xin, gXTH, NF, NF, 0);
        hgemm<<<dim3(NS / BN, NI3 / BM, NB), 256, SMEM_DYN>>>(
            gW0H + (size_t)d * NI3 * NF, NF, 0, gXTH, NF, NF / 32, 0, nullptr, nullptr);
        linattn_kernel<<<dim3(NI, NB), 256>>>();

        transpose_h_kernel<<<dim3(NS / 32, NI / 32, NB), tb>>>(gV, gVTH, NI, NI, 0);
        hgemm<<<dim3(NS / BN, NI3 / BM, NB), 256, SMEM_DYN>>>(
            gW1H + (size_t)d * NKT * NI3 * NI, NI, 1, gVTH, NI, NKT * NI / 32,
            0, nullptr, nullptr);
        linattn_kernel<<<dim3(NI, NB), 256>>>();

        transpose_h_kernel<<<dim3(NS / 32, NI / 32, NB), tb>>>(gV, gVTH, NI, NI, 0);
        hgemm<<<dim3(NS / BN, NF / BM, NB), 256, SMEM_DYN>>>(
            gW2H + (size_t)d * NF * NI, NI, 0, gVTH, NI, NI / 32, accm, nullptr, nullptr);
    }

    // final: concat(P;Q) -> [b][s][512] half, then out = out_w @ concat + bias
    transpose_h_kernel<<<dim3(NS / 32, NF / 32, NB), tb>>>(gP, gVTH, NF, 2 * NF, 0);
    transpose_h_kernel<<<dim3(NS / 32, NF / 32, NB), tb>>>(gQ, gVTH, NF, 2 * NF, NF);
    hgemm<<<dim3(NS / BN, NV / BM, NB), 256, SMEM_DYN>>>(
        gOWH, 2 * NF, 0, gVTH, 2 * NF, 2 * NF / 32, 3, out, out_b);
}